// round 12
// baseline (speedup 1.0000x reference)
#include <cuda_runtime.h>
#include <cuda_fp16.h>
#include <cstdint>

#define GRIDS 64
#define GP    65            // GRIDS + 1
#define ODIM  128
#define PDIM  64            // INPUT_DIM / 2
#define BATCH 16384
#define CELLS (GP * GP)     // 4225
#define BT    32            // batch tile per block
#define TGRID 304           // persistent transpose grid (152 SM x 2)

// fp16 transposed table: fp_t[p][cell][o], cell = ia*65 + ib
__device__ __half g_fpt[(size_t)PDIM * CELLS * ODIM];   // ~69 MB

// ---------------------------------------------------------------------------
// Kernel 1: transpose + fp32->fp16 convert (R6 body, persistent grid-stride).
// Every block triggers programmatic launch completion at start so kan_main
// can begin its table-independent prologue immediately.
// ---------------------------------------------------------------------------
__global__ __launch_bounds__(256) void kan_transpose(const float* __restrict__ fp) {
    __shared__ float tile[ODIM * (PDIM + 1)];   // [o][p], pad 65

    if (threadIdx.x == 0) cudaTriggerProgrammaticLaunchCompletion();

    for (int cell = blockIdx.x; cell < CELLS; cell += TGRID) {
        __syncthreads();   // protect tile reuse across iterations
        const float4* src = reinterpret_cast<const float4*>(fp + (size_t)cell * (ODIM * PDIM));

        for (int idx = threadIdx.x; idx < (ODIM * PDIM) / 4; idx += 256) {
            int o  = idx >> 4;
            int p4 = (idx & 15) << 2;
            float4 v = src[idx];
            float* row = &tile[o * (PDIM + 1) + p4];
            row[0] = v.x; row[1] = v.y; row[2] = v.z; row[3] = v.w;
        }
        __syncthreads();

        __half2* dst2 = reinterpret_cast<__half2*>(g_fpt);
        for (int idx = threadIdx.x; idx < (ODIM * PDIM) / 2; idx += 256) {
            int p  = idx >> 6;
            int o2 = idx & 63;
            float lo = tile[(2 * o2) * (PDIM + 1) + p];
            float hi = tile[(2 * o2 + 1) * (PDIM + 1) + p];
            dst2[((size_t)p * CELLS + cell) * (ODIM / 2) + o2] =
                __floats2half2_rn(lo, hi);
        }
    }
}

// ---------------------------------------------------------------------------
// Kernel 2: main gather + bilinear reduction (exact R7 body + PDL sync).
// Block: 512 threads = 16 o-groups (8 outputs each) x 32 batch columns.
// Prologue (no table access) runs concurrently with the transpose; the
// gather loop starts after cudaGridDependencySynchronize().
// ---------------------------------------------------------------------------
__global__ __launch_bounds__(512, 2) void kan_main(const float* __restrict__ x,
                                                   const float* __restrict__ borders,
                                                   const float* __restrict__ invlen,
                                                   float* __restrict__ out) {
    __shared__ float sb[GP];
    __shared__ float sl[GRIDS];
    __shared__ int   s_cell[PDIM][BT];
    __shared__ uint2 s_wq[PDIM][BT];     // 4 packed half weights
    __shared__ float so[ODIM][BT + 1];   // epilogue transpose buffer

    const int t  = threadIdx.x;
    const int og = t & 15;     // o-group: owns outputs og*8 .. og*8+7
    const int bi = t >> 4;     // batch index within tile, 0..31
    const int b0 = blockIdx.x * BT;

    if (t < GP)                 sb[t] = borders[t];
    else if (t < GP + GRIDS)    sl[t - GP] = invlen[t - GP];
    __syncthreads();

    // Prologue: indices + packed interpolation weights for all (p, b).
    for (int i = t; i < PDIM * BT; i += 512) {
        int p = i >> 5;        // /32
        int b = i & 31;
        float v1 = x[(size_t)(2 * p) * BATCH + b0 + b];
        float v2 = x[(size_t)(2 * p + 1) * BATCH + b0 + b];

        float e1 = expf(-fabsf(v1));
        float c1 = (v1 > 0.f) ? (1.f - 0.5f * e1) : (0.5f * e1);
        int i1 = (int)(c1 * (float)GRIDS);
        i1 = i1 < 0 ? 0 : (i1 > GRIDS - 1 ? GRIDS - 1 : i1);

        float e2 = expf(-fabsf(v2));
        float c2 = (v2 > 0.f) ? (1.f - 0.5f * e2) : (0.5f * e2);
        int i2 = (int)(c2 * (float)GRIDS);
        i2 = i2 < 0 ? 0 : (i2 > GRIDS - 1 ? GRIDS - 1 : i2);

        float d1 = (v1 - sb[i1]) * sl[i1];
        float d2 = (v2 - sb[i2]) * sl[i2];
        float w11 = d1 * d2;
        float w10 = d1 - w11;
        float w01 = d2 - w11;
        float w00 = 1.f - d1 - w01;

        s_cell[p][b] = i1 * GP + i2;
        __half2 hA = __floats2half2_rn(w00, w01);   // lanes: (w00, w01)
        __half2 hB = __floats2half2_rn(w10, w11);   // lanes: (w10, w11)
        uint2 wq;
        wq.x = *reinterpret_cast<unsigned*>(&hA);
        wq.y = *reinterpret_cast<unsigned*>(&hB);
        s_wq[p][b] = wq;
    }
    __syncthreads();

    // Wait for the transpose (table producer) to fully complete.
    cudaGridDependencySynchronize();

    float acc[8] = {0.f, 0.f, 0.f, 0.f, 0.f, 0.f, 0.f, 0.f};
    const __half* __restrict__ tab = g_fpt;
    const int oofs = og * 8;

    for (int pg = 0; pg < PDIM / 4; ++pg) {
        __half2 hacc[4];
#pragma unroll
        for (int q = 0; q < 4; ++q) {
            const int p = pg * 4 + q;
            const int   c  = s_cell[p][bi];
            const uint2 wq = s_wq[p][bi];
            const __half2 hA = *reinterpret_cast<const __half2*>(&wq.x);
            const __half2 hB = *reinterpret_cast<const __half2*>(&wq.y);
            const __half2 h00 = __half2half2(__low2half(hA));
            const __half2 h01 = __half2half2(__high2half(hA));
            const __half2 h10 = __half2half2(__low2half(hB));
            const __half2 h11 = __half2half2(__high2half(hB));

            const __half* base = tab + ((size_t)p * CELLS + c) * ODIM + oofs;
            uint4 a0 = *reinterpret_cast<const uint4*>(base);                   // (i1,   i2  )
            uint4 a1 = *reinterpret_cast<const uint4*>(base + ODIM);            // (i1,   i2+1)
            uint4 a2 = *reinterpret_cast<const uint4*>(base + GP * ODIM);       // (i1+1, i2  )
            uint4 a3 = *reinterpret_cast<const uint4*>(base + (GP + 1) * ODIM); // (i1+1, i2+1)

            const unsigned* u0 = &a0.x;
            const unsigned* u1 = &a1.x;
            const unsigned* u2 = &a2.x;
            const unsigned* u3 = &a3.x;
#pragma unroll
            for (int j = 0; j < 4; ++j) {
                __half2 v0 = *reinterpret_cast<const __half2*>(&u0[j]);
                __half2 v1 = *reinterpret_cast<const __half2*>(&u1[j]);
                __half2 v2 = *reinterpret_cast<const __half2*>(&u2[j]);
                __half2 v3 = *reinterpret_cast<const __half2*>(&u3[j]);
                __half2 s = __hmul2(h00, v0);
                s = __hfma2(h01, v1, s);
                s = __hfma2(h10, v2, s);
                s = __hfma2(h11, v3, s);
                if (q == 0) hacc[j] = s;
                else        hacc[j] = __hadd2(hacc[j], s);
            }
        }
#pragma unroll
        for (int j = 0; j < 4; ++j) {
            float2 f = __half22float2(hacc[j]);
            acc[2 * j]     += f.x;
            acc[2 * j + 1] += f.y;
        }
    }

    // Epilogue: transpose through smem for coalesced 128B row stores.
    __syncthreads();
#pragma unroll
    for (int k = 0; k < 8; ++k) so[oofs + k][bi] = acc[k];
    __syncthreads();
    for (int idx = t; idx < ODIM * BT; idx += 512) {
        int o = idx >> 5;   // /32
        int j = idx & 31;
        out[(size_t)o * BATCH + b0 + j] = so[o][j];
    }
}

extern "C" void kernel_launch(void* const* d_in, const int* in_sizes, int n_in,
                              void* d_out, int out_size) {
    const float* x       = (const float*)d_in[0];
    const float* fp      = (const float*)d_in[1];
    const float* borders = (const float*)d_in[2];
    const float* invlen  = (const float*)d_in[3];
    float* out = (float*)d_out;

    kan_transpose<<<TGRID, 256>>>(fp);

    // Launch kan_main with programmatic stream serialization (PDL): it may
    // start while kan_transpose is still running; the device-side
    // cudaGridDependencySynchronize() provides the real dependency.
    cudaLaunchConfig_t cfg = {};
    cfg.gridDim  = dim3(BATCH / BT, 1, 1);
    cfg.blockDim = dim3(512, 1, 1);
    cfg.dynamicSmemBytes = 0;
    cfg.stream = 0;
    cudaLaunchAttribute attrs[1];
    attrs[0].id = cudaLaunchAttributeProgrammaticStreamSerialization;
    attrs[0].val.programmaticStreamSerializationAllowed = 1;
    cfg.attrs = attrs;
    cfg.numAttrs = 1;
    cudaError_t err = cudaLaunchKernelEx(&cfg, kan_main, x, borders, invlen, out);
    if (err != cudaSuccess) {
        // Fallback: plain sequential launch (still correct).
        kan_main<<<BATCH / BT, 512>>>(x, borders, invlen, out);
    }
}

// round 13
// speedup vs baseline: 1.0036x; 1.0036x over previous
#include <cuda_runtime.h>
#include <cuda_fp16.h>
#include <cstdint>

#define GRIDS 64
#define GP    65            // GRIDS + 1
#define ODIM  128
#define PDIM  64            // INPUT_DIM / 2
#define BATCH 16384
#define CELLS (GP * GP)     // 4225
#define BT    32            // batch tile per block

// fp16 transposed table: fp_t[p][cell][o], cell = ia*65 + ib
__device__ __half g_fpt[(size_t)PDIM * CELLS * ODIM];   // ~69 MB

// ---------------------------------------------------------------------------
// Kernel 1: transpose + fp32->fp16 convert (exact R6 body, block per cell).
// Each block triggers programmatic launch completion at start so the
// dependent kan_main can begin its table-independent prologue early.
// ---------------------------------------------------------------------------
__global__ __launch_bounds__(256) void kan_transpose(const float* __restrict__ fp) {
    __shared__ float tile[ODIM * (PDIM + 1)];   // [o][p], pad 65
    const int cell = blockIdx.x;
    const float4* src = reinterpret_cast<const float4*>(fp + (size_t)cell * (ODIM * PDIM));

    if (threadIdx.x == 0) cudaTriggerProgrammaticLaunchCompletion();

    for (int idx = threadIdx.x; idx < (ODIM * PDIM) / 4; idx += 256) {
        int o  = idx >> 4;
        int p4 = (idx & 15) << 2;
        float4 v = src[idx];
        float* row = &tile[o * (PDIM + 1) + p4];
        row[0] = v.x; row[1] = v.y; row[2] = v.z; row[3] = v.w;
    }
    __syncthreads();

    __half2* dst2 = reinterpret_cast<__half2*>(g_fpt);
    for (int idx = threadIdx.x; idx < (ODIM * PDIM) / 2; idx += 256) {
        int p  = idx >> 6;
        int o2 = idx & 63;
        float lo = tile[(2 * o2) * (PDIM + 1) + p];
        float hi = tile[(2 * o2 + 1) * (PDIM + 1) + p];
        dst2[((size_t)p * CELLS + cell) * (ODIM / 2) + o2] =
            __floats2half2_rn(lo, hi);
    }
}

// ---------------------------------------------------------------------------
// Kernel 2: main gather + bilinear reduction (exact R7 body + PDL sync).
// Block: 512 threads = 16 o-groups (8 outputs each) x 32 batch columns.
// Prologue (no table access) may overlap the transpose tail; the gather
// loop starts after cudaGridDependencySynchronize().
// ---------------------------------------------------------------------------
__global__ __launch_bounds__(512, 2) void kan_main(const float* __restrict__ x,
                                                   const float* __restrict__ borders,
                                                   const float* __restrict__ invlen,
                                                   float* __restrict__ out) {
    __shared__ float sb[GP];
    __shared__ float sl[GRIDS];
    __shared__ int   s_cell[PDIM][BT];
    __shared__ uint2 s_wq[PDIM][BT];     // 4 packed half weights
    __shared__ float so[ODIM][BT + 1];   // epilogue transpose buffer

    const int t  = threadIdx.x;
    const int og = t & 15;     // o-group: owns outputs og*8 .. og*8+7
    const int bi = t >> 4;     // batch index within tile, 0..31
    const int b0 = blockIdx.x * BT;

    if (t < GP)                 sb[t] = borders[t];
    else if (t < GP + GRIDS)    sl[t - GP] = invlen[t - GP];
    __syncthreads();

    // Prologue: indices + packed interpolation weights for all (p, b).
    for (int i = t; i < PDIM * BT; i += 512) {
        int p = i >> 5;        // /32
        int b = i & 31;
        float v1 = x[(size_t)(2 * p) * BATCH + b0 + b];
        float v2 = x[(size_t)(2 * p + 1) * BATCH + b0 + b];

        float e1 = expf(-fabsf(v1));
        float c1 = (v1 > 0.f) ? (1.f - 0.5f * e1) : (0.5f * e1);
        int i1 = (int)(c1 * (float)GRIDS);
        i1 = i1 < 0 ? 0 : (i1 > GRIDS - 1 ? GRIDS - 1 : i1);

        float e2 = expf(-fabsf(v2));
        float c2 = (v2 > 0.f) ? (1.f - 0.5f * e2) : (0.5f * e2);
        int i2 = (int)(c2 * (float)GRIDS);
        i2 = i2 < 0 ? 0 : (i2 > GRIDS - 1 ? GRIDS - 1 : i2);

        float d1 = (v1 - sb[i1]) * sl[i1];
        float d2 = (v2 - sb[i2]) * sl[i2];
        float w11 = d1 * d2;
        float w10 = d1 - w11;
        float w01 = d2 - w11;
        float w00 = 1.f - d1 - w01;

        s_cell[p][b] = i1 * GP + i2;
        __half2 hA = __floats2half2_rn(w00, w01);   // lanes: (w00, w01)
        __half2 hB = __floats2half2_rn(w10, w11);   // lanes: (w10, w11)
        uint2 wq;
        wq.x = *reinterpret_cast<unsigned*>(&hA);
        wq.y = *reinterpret_cast<unsigned*>(&hB);
        s_wq[p][b] = wq;
    }
    __syncthreads();

    // Wait for the transpose (table producer) to fully complete.
    cudaGridDependencySynchronize();

    float acc[8] = {0.f, 0.f, 0.f, 0.f, 0.f, 0.f, 0.f, 0.f};
    const __half* __restrict__ tab = g_fpt;
    const int oofs = og * 8;

    for (int pg = 0; pg < PDIM / 4; ++pg) {
        __half2 hacc[4];
#pragma unroll
        for (int q = 0; q < 4; ++q) {
            const int p = pg * 4 + q;
            const int   c  = s_cell[p][bi];
            const uint2 wq = s_wq[p][bi];
            const __half2 hA = *reinterpret_cast<const __half2*>(&wq.x);
            const __half2 hB = *reinterpret_cast<const __half2*>(&wq.y);
            const __half2 h00 = __half2half2(__low2half(hA));
            const __half2 h01 = __half2half2(__high2half(hA));
            const __half2 h10 = __half2half2(__low2half(hB));
            const __half2 h11 = __half2half2(__high2half(hB));

            const __half* base = tab + ((size_t)p * CELLS + c) * ODIM + oofs;
            uint4 a0 = *reinterpret_cast<const uint4*>(base);                   // (i1,   i2  )
            uint4 a1 = *reinterpret_cast<const uint4*>(base + ODIM);            // (i1,   i2+1)
            uint4 a2 = *reinterpret_cast<const uint4*>(base + GP * ODIM);       // (i1+1, i2  )
            uint4 a3 = *reinterpret_cast<const uint4*>(base + (GP + 1) * ODIM); // (i1+1, i2+1)

            const unsigned* u0 = &a0.x;
            const unsigned* u1 = &a1.x;
            const unsigned* u2 = &a2.x;
            const unsigned* u3 = &a3.x;
#pragma unroll
            for (int j = 0; j < 4; ++j) {
                __half2 v0 = *reinterpret_cast<const __half2*>(&u0[j]);
                __half2 v1 = *reinterpret_cast<const __half2*>(&u1[j]);
                __half2 v2 = *reinterpret_cast<const __half2*>(&u2[j]);
                __half2 v3 = *reinterpret_cast<const __half2*>(&u3[j]);
                __half2 s = __hmul2(h00, v0);
                s = __hfma2(h01, v1, s);
                s = __hfma2(h10, v2, s);
                s = __hfma2(h11, v3, s);
                if (q == 0) hacc[j] = s;
                else        hacc[j] = __hadd2(hacc[j], s);
            }
        }
#pragma unroll
        for (int j = 0; j < 4; ++j) {
            float2 f = __half22float2(hacc[j]);
            acc[2 * j]     += f.x;
            acc[2 * j + 1] += f.y;
        }
    }

    // Epilogue: transpose through smem for coalesced 128B row stores.
    __syncthreads();
#pragma unroll
    for (int k = 0; k < 8; ++k) so[oofs + k][bi] = acc[k];
    __syncthreads();
    for (int idx = t; idx < ODIM * BT; idx += 512) {
        int o = idx >> 5;   // /32
        int j = idx & 31;
        out[(size_t)o * BATCH + b0 + j] = so[o][j];
    }
}

extern "C" void kernel_launch(void* const* d_in, const int* in_sizes, int n_in,
                              void* d_out, int out_size) {
    const float* x       = (const float*)d_in[0];
    const float* fp      = (const float*)d_in[1];
    const float* borders = (const float*)d_in[2];
    const float* invlen  = (const float*)d_in[3];
    float* out = (float*)d_out;

    kan_transpose<<<CELLS, 256>>>(fp);

    // PDL: kan_main may start while kan_transpose finishes; the device-side
    // cudaGridDependencySynchronize() provides the real data dependency.
    cudaLaunchConfig_t cfg = {};
    cfg.gridDim  = dim3(BATCH / BT, 1, 1);
    cfg.blockDim = dim3(512, 1, 1);
    cfg.dynamicSmemBytes = 0;
    cfg.stream = 0;
    cudaLaunchAttribute attrs[1];
    attrs[0].id = cudaLaunchAttributeProgrammaticStreamSerialization;
    attrs[0].val.programmaticStreamSerializationAllowed = 1;
    cfg.attrs = attrs;
    cfg.numAttrs = 1;
    cudaError_t err = cudaLaunchKernelEx(&cfg, kan_main, x, borders, invlen, out);
    if (err != cudaSuccess) {
        // Fallback: plain sequential launch (still correct).
        kan_main<<<BATCH / BT, 512>>>(x, borders, invlen, out);
    }
}

// round 14
// speedup vs baseline: 1.3523x; 1.3475x over previous
#include <cuda_runtime.h>
#include <cuda_fp16.h>
#include <cstdint>

#define GRIDS 64
#define GP    65            // GRIDS + 1
#define ODIM  128
#define PDIM  64            // INPUT_DIM / 2
#define BATCH 16384
#define CELLS (GP * GP)     // 4225
#define BT    32            // batch tile per block

// fp16 transposed table: fp_t[p][cell][o], cell = ia*65 + ib
__device__ __half g_fpt[(size_t)PDIM * CELLS * ODIM];   // ~69 MB

// ---------------------------------------------------------------------------
// Kernel 1: transpose + fp32->fp16 convert (R6 body; streaming source reads).
// ---------------------------------------------------------------------------
__global__ __launch_bounds__(256) void kan_transpose(const float* __restrict__ fp) {
    __shared__ float tile[ODIM * (PDIM + 1)];   // [o][p], pad 65
    const int cell = blockIdx.x;
    const float4* src = reinterpret_cast<const float4*>(fp + (size_t)cell * (ODIM * PDIM));

    for (int idx = threadIdx.x; idx < (ODIM * PDIM) / 4; idx += 256) {
        int o  = idx >> 4;
        int p4 = (idx & 15) << 2;
        float4 v = __ldcs(&src[idx]);   // streaming: don't pollute L2
        float* row = &tile[o * (PDIM + 1) + p4];
        row[0] = v.x; row[1] = v.y; row[2] = v.z; row[3] = v.w;
    }
    __syncthreads();

    __half2* dst2 = reinterpret_cast<__half2*>(g_fpt);
    for (int idx = threadIdx.x; idx < (ODIM * PDIM) / 2; idx += 256) {
        int p  = idx >> 6;
        int o2 = idx & 63;
        float lo = tile[(2 * o2) * (PDIM + 1) + p];
        float hi = tile[(2 * o2 + 1) * (PDIM + 1) + p];
        dst2[((size_t)p * CELLS + cell) * (ODIM / 2) + o2] =
            __floats2half2_rn(lo, hi);
    }
}

// ---------------------------------------------------------------------------
// Kernel 2: main gather + bilinear reduction (exact R7 body).
// Block: 512 threads = 16 o-groups (8 outputs each) x 32 batch columns.
// Groups of 4 p-iterations accumulate in half2, flush to fp32 per group.
// ---------------------------------------------------------------------------
__global__ __launch_bounds__(512, 2) void kan_main(const float* __restrict__ x,
                                                   const float* __restrict__ borders,
                                                   const float* __restrict__ invlen,
                                                   float* __restrict__ out) {
    __shared__ float sb[GP];
    __shared__ float sl[GRIDS];
    __shared__ int   s_cell[PDIM][BT];
    __shared__ uint2 s_wq[PDIM][BT];     // 4 packed half weights
    __shared__ float so[ODIM][BT + 1];   // epilogue transpose buffer

    const int t  = threadIdx.x;
    const int og = t & 15;     // o-group: owns outputs og*8 .. og*8+7
    const int bi = t >> 4;     // batch index within tile, 0..31
    const int b0 = blockIdx.x * BT;

    if (t < GP)                 sb[t] = borders[t];
    else if (t < GP + GRIDS)    sl[t - GP] = invlen[t - GP];
    __syncthreads();

    // Prologue: indices + packed interpolation weights for all (p, b).
    for (int i = t; i < PDIM * BT; i += 512) {
        int p = i >> 5;        // /32
        int b = i & 31;
        float v1 = x[(size_t)(2 * p) * BATCH + b0 + b];
        float v2 = x[(size_t)(2 * p + 1) * BATCH + b0 + b];

        float e1 = expf(-fabsf(v1));
        float c1 = (v1 > 0.f) ? (1.f - 0.5f * e1) : (0.5f * e1);
        int i1 = (int)(c1 * (float)GRIDS);
        i1 = i1 < 0 ? 0 : (i1 > GRIDS - 1 ? GRIDS - 1 : i1);

        float e2 = expf(-fabsf(v2));
        float c2 = (v2 > 0.f) ? (1.f - 0.5f * e2) : (0.5f * e2);
        int i2 = (int)(c2 * (float)GRIDS);
        i2 = i2 < 0 ? 0 : (i2 > GRIDS - 1 ? GRIDS - 1 : i2);

        float d1 = (v1 - sb[i1]) * sl[i1];
        float d2 = (v2 - sb[i2]) * sl[i2];
        float w11 = d1 * d2;
        float w10 = d1 - w11;
        float w01 = d2 - w11;
        float w00 = 1.f - d1 - w01;

        s_cell[p][b] = i1 * GP + i2;
        __half2 hA = __floats2half2_rn(w00, w01);   // lanes: (w00, w01)
        __half2 hB = __floats2half2_rn(w10, w11);   // lanes: (w10, w11)
        uint2 wq;
        wq.x = *reinterpret_cast<unsigned*>(&hA);
        wq.y = *reinterpret_cast<unsigned*>(&hB);
        s_wq[p][b] = wq;
    }
    __syncthreads();

    float acc[8] = {0.f, 0.f, 0.f, 0.f, 0.f, 0.f, 0.f, 0.f};
    const __half* __restrict__ tab = g_fpt;
    const int oofs = og * 8;

    for (int pg = 0; pg < PDIM / 4; ++pg) {
        __half2 hacc[4];
#pragma unroll
        for (int q = 0; q < 4; ++q) {
            const int p = pg * 4 + q;
            const int   c  = s_cell[p][bi];
            const uint2 wq = s_wq[p][bi];
            const __half2 hA = *reinterpret_cast<const __half2*>(&wq.x);
            const __half2 hB = *reinterpret_cast<const __half2*>(&wq.y);
            const __half2 h00 = __half2half2(__low2half(hA));
            const __half2 h01 = __half2half2(__high2half(hA));
            const __half2 h10 = __half2half2(__low2half(hB));
            const __half2 h11 = __half2half2(__high2half(hB));

            const __half* base = tab + ((size_t)p * CELLS + c) * ODIM + oofs;
            uint4 a0 = *reinterpret_cast<const uint4*>(base);                   // (i1,   i2  )
            uint4 a1 = *reinterpret_cast<const uint4*>(base + ODIM);            // (i1,   i2+1)
            uint4 a2 = *reinterpret_cast<const uint4*>(base + GP * ODIM);       // (i1+1, i2  )
            uint4 a3 = *reinterpret_cast<const uint4*>(base + (GP + 1) * ODIM); // (i1+1, i2+1)

            const unsigned* u0 = &a0.x;
            const unsigned* u1 = &a1.x;
            const unsigned* u2 = &a2.x;
            const unsigned* u3 = &a3.x;
#pragma unroll
            for (int j = 0; j < 4; ++j) {
                __half2 v0 = *reinterpret_cast<const __half2*>(&u0[j]);
                __half2 v1 = *reinterpret_cast<const __half2*>(&u1[j]);
                __half2 v2 = *reinterpret_cast<const __half2*>(&u2[j]);
                __half2 v3 = *reinterpret_cast<const __half2*>(&u3[j]);
                __half2 s = __hmul2(h00, v0);
                s = __hfma2(h01, v1, s);
                s = __hfma2(h10, v2, s);
                s = __hfma2(h11, v3, s);
                if (q == 0) hacc[j] = s;
                else        hacc[j] = __hadd2(hacc[j], s);
            }
        }
#pragma unroll
        for (int j = 0; j < 4; ++j) {
            float2 f = __half22float2(hacc[j]);
            acc[2 * j]     += f.x;
            acc[2 * j + 1] += f.y;
        }
    }

    // Epilogue: transpose through smem for coalesced 128B row stores.
    __syncthreads();
#pragma unroll
    for (int k = 0; k < 8; ++k) so[oofs + k][bi] = acc[k];
    __syncthreads();
    for (int idx = t; idx < ODIM * BT; idx += 512) {
        int o = idx >> 5;   // /32
        int j = idx & 31;
        out[(size_t)o * BATCH + b0 + j] = so[o][j];
    }
}

extern "C" void kernel_launch(void* const* d_in, const int* in_sizes, int n_in,
                              void* d_out, int out_size) {
    const float* x       = (const float*)d_in[0];
    const float* fp      = (const float*)d_in[1];
    const float* borders = (const float*)d_in[2];
    const float* invlen  = (const float*)d_in[3];
    float* out = (float*)d_out;

    kan_transpose<<<CELLS, 256>>>(fp);
    kan_main<<<BATCH / BT, 512>>>(x, borders, invlen, out);
}